// round 1
// baseline (speedup 1.0000x reference)
#include <cuda_runtime.h>
#include <cuda_bf16.h>

// Problem constants
#define BATCH 16
#define SEQ   1024
#define INP   384
#define HEADS 8
#define DHEAD 32
#define INNER 256            // HEADS * DHEAD
#define QKV3  768            // 3 * INNER
#define OUP   384
#define SCALE 0.17677669529663687f   // 32^-0.5

// ---------------- scratch (device globals; no allocations allowed) ----------
__device__ float g_qkv [BATCH * SEQ * QKV3];    // [b, n, 768]
__device__ float g_bias[HEADS * SEQ * SEQ];     // [h, i, j]
__device__ float g_attn[BATCH * SEQ * INNER];   // [b, n, h*32+d]

// ---------------- generic fp32 tiled GEMM: C = A[M,K] @ B[K,N] (+bias) ------
template<int BM, int BN, int BK, int TM, int TN, bool HAS_BIAS>
__global__ __launch_bounds__(256) void gemm_kernel(
    const float* __restrict__ A, const float* __restrict__ Bm,
    const float* __restrict__ bias, float* __restrict__ C,
    int M, int Ncol, int K)
{
    __shared__ float As[BK][BM];   // transposed A tile
    __shared__ float Bs[BK][BN];

    const int tid = threadIdx.x;
    const int tx  = tid & ((BN / TN) - 1);   // 0..15
    const int ty  = tid / (BN / TN);         // 0..15
    const int m0  = blockIdx.y * BM;
    const int n0  = blockIdx.x * BN;

    float acc[TM][TN];
#pragma unroll
    for (int i = 0; i < TM; i++)
#pragma unroll
        for (int j = 0; j < TN; j++) acc[i][j] = 0.0f;

    for (int k0 = 0; k0 < K; k0 += BK) {
        // Load A tile: BM x BK = 128x16 floats = 512 float4, 2 per thread
#pragma unroll
        for (int p = 0; p < (BM * BK) / (256 * 4); p++) {
            int slot = tid + p * 256;
            int r  = slot >> 2;           // row within tile (0..127)
            int c4 = (slot & 3) * 4;      // k offset
            float4 av = *(const float4*)(A + (size_t)(m0 + r) * K + k0 + c4);
            As[c4 + 0][r] = av.x;
            As[c4 + 1][r] = av.y;
            As[c4 + 2][r] = av.z;
            As[c4 + 3][r] = av.w;
        }
        // Load B tile: BK x BN = 16x64 floats = 256 float4, 1 per thread
        {
            int r  = tid >> 4;            // 0..15
            int c4 = (tid & 15) * 4;      // 0..60
            *(float4*)&Bs[r][c4] =
                *(const float4*)(Bm + (size_t)(k0 + r) * Ncol + n0 + c4);
        }
        __syncthreads();

#pragma unroll
        for (int k = 0; k < BK; k++) {
            float4 bv = *(const float4*)&Bs[k][tx * TN];
            float a[TM];
#pragma unroll
            for (int i = 0; i < TM; i++) a[i] = As[k][ty * TM + i];
#pragma unroll
            for (int i = 0; i < TM; i++) {
                acc[i][0] += a[i] * bv.x;
                acc[i][1] += a[i] * bv.y;
                acc[i][2] += a[i] * bv.z;
                acc[i][3] += a[i] * bv.w;
            }
        }
        __syncthreads();
    }

    float bx = 0.f, by = 0.f, bz = 0.f, bw = 0.f;
    if (HAS_BIAS) {
        const float* bb = bias + n0 + tx * TN;
        bx = bb[0]; by = bb[1]; bz = bb[2]; bw = bb[3];
    }
#pragma unroll
    for (int i = 0; i < TM; i++) {
        float4 r;
        r.x = acc[i][0] + bx;
        r.y = acc[i][1] + by;
        r.z = acc[i][2] + bz;
        r.w = acc[i][3] + bw;
        *(float4*)(C + (size_t)(m0 + ty * TM + i) * Ncol + n0 + tx * TN) = r;
    }
}

// ---------------- bias gather: g_bias[h][i*1024+j] = table[rel[i,j]*8 + h] ---
__global__ __launch_bounds__(256) void bias_expand_kernel(
    const int* __restrict__ rel, const float* __restrict__ table)
{
    int ij = blockIdx.x * blockDim.x + threadIdx.x;   // 0 .. 1048575
    int idx = rel[ij];
    const float* t = table + idx * 8;
#pragma unroll
    for (int h = 0; h < HEADS; h++)
        g_bias[(size_t)h * (SEQ * SEQ) + ij] = __ldg(t + h);
}

// ---------------- flash-style attention -------------------------------------
// grid = (8 i-tiles, 8 heads, 16 batches); 128 threads; 1 query row / thread
__global__ __launch_bounds__(128) void attn_kernel()
{
    __shared__ float Ks[32][36];   // 144B row stride: 16B aligned, broadcast reads
    __shared__ float Vs[32][36];

    const int it  = blockIdx.x;
    const int h   = blockIdx.y;
    const int b   = blockIdx.z;
    const int tid = threadIdx.x;           // 0..127
    const int row = it * 128 + tid;        // query index i

    // Load q row into registers (uncoalesced but once per CTA; L1-friendly)
    const float* qbase = g_qkv + ((size_t)(b * SEQ + row)) * QKV3 + h * DHEAD;
    float q[32];
#pragma unroll
    for (int d4 = 0; d4 < 8; d4++) {
        float4 v = *(const float4*)(qbase + d4 * 4);
        q[d4 * 4 + 0] = v.x; q[d4 * 4 + 1] = v.y;
        q[d4 * 4 + 2] = v.z; q[d4 * 4 + 3] = v.w;
    }

    float o[32];
#pragma unroll
    for (int d = 0; d < 32; d++) o[d] = 0.0f;
    float mrun = -1e30f, lrun = 0.0f;

    const float* biasrow = g_bias + ((size_t)h * SEQ * SEQ) + (size_t)row * SEQ;

    for (int j0 = 0; j0 < SEQ; j0 += 32) {
        // Cooperatively stage K and V 32x32 tiles (coalesced-ish float4 loads)
#pragma unroll
        for (int p = 0; p < 2; p++) {
            int slot = tid + p * 128;
            int r  = slot >> 3;            // 0..31
            int c4 = (slot & 7) * 4;       // 0..28
            const float* kb = g_qkv + ((size_t)(b * SEQ + j0 + r)) * QKV3
                              + INNER + h * DHEAD + c4;
            *(float4*)&Ks[r][c4] = *(const float4*)kb;
            *(float4*)&Vs[r][c4] = *(const float4*)(kb + INNER);
        }
        __syncthreads();

        // S row segment
        float p_[32];
        float tmax = -1e30f;
#pragma unroll
        for (int j = 0; j < 32; j++) {
            float s = 0.0f;
#pragma unroll
            for (int d = 0; d < 32; d++) s += q[d] * Ks[j][d];
            s = s * SCALE + biasrow[j0 + j];
            p_[j] = s;
            tmax = fmaxf(tmax, s);
        }

        // online softmax update
        float mnew  = fmaxf(mrun, tmax);
        float alpha = __expf(mrun - mnew);
        lrun *= alpha;
#pragma unroll
        for (int d = 0; d < 32; d++) o[d] *= alpha;

#pragma unroll
        for (int j = 0; j < 32; j++) {
            float pj = __expf(p_[j] - mnew);
            lrun += pj;
#pragma unroll
            for (int d = 0; d < 32; d++) o[d] += pj * Vs[j][d];
        }
        mrun = mnew;
        __syncthreads();
    }

    float inv = 1.0f / lrun;
    float* ob = g_attn + ((size_t)(b * SEQ + row)) * INNER + h * DHEAD;
#pragma unroll
    for (int d4 = 0; d4 < 8; d4++) {
        float4 v;
        v.x = o[d4 * 4 + 0] * inv; v.y = o[d4 * 4 + 1] * inv;
        v.z = o[d4 * 4 + 2] * inv; v.w = o[d4 * 4 + 3] * inv;
        *(float4*)(ob + d4 * 4) = v;
    }
}

// ---------------- launch -----------------------------------------------------
extern "C" void kernel_launch(void* const* d_in, const int* in_sizes, int n_in,
                              void* d_out, int out_size)
{
    const float* x      = (const float*)d_in[0];   // [16,1024,384]
    const float* w_qkv  = (const float*)d_in[1];   // [384,768]
    const float* table  = (const float*)d_in[2];   // [3969,8]
    const float* w_out  = (const float*)d_in[3];   // [256,384]
    const float* b_out  = (const float*)d_in[4];   // [384]
    const int*   relidx = (const int*)  d_in[5];   // [1024,1024]
    float* out = (float*)d_out;                    // [16,1024,384]

    float* qkv_ptr  = nullptr;
    float* attn_ptr = nullptr;
    cudaGetSymbolAddress((void**)&qkv_ptr,  g_qkv);
    cudaGetSymbolAddress((void**)&attn_ptr, g_attn);

    const int M = BATCH * SEQ;   // 16384

    // 1) qkv = x @ w_qkv
    gemm_kernel<128, 64, 16, 8, 4, false>
        <<<dim3(QKV3 / 64, M / 128), 256>>>(x, w_qkv, nullptr, qkv_ptr,
                                            M, QKV3, INP);
    // 2) expand relative bias per head
    bias_expand_kernel<<<(SEQ * SEQ) / 256, 256>>>(relidx, table);

    // 3) attention (flash-style, fused softmax+bias)
    attn_kernel<<<dim3(SEQ / 128, HEADS, BATCH), 128>>>();

    // 4) out = attn @ w_out + b_out
    gemm_kernel<128, 64, 16, 8, 4, true>
        <<<dim3(OUP / 64, M / 128), 256>>>(attn_ptr, w_out, b_out, out,
                                           M, OUP, INNER);
}

// round 3
// speedup vs baseline: 2.2389x; 2.2389x over previous
#include <cuda_runtime.h>
#include <cuda_bf16.h>

#define BATCH 16
#define SEQ   1024
#define INP   384
#define HEADS 8
#define INNER 256
#define QKV3  768
#define OUP   384
#define SCALE 0.17677669529663687f
#define L2E   1.4426950408889634f

// ---------------- scratch ----------------------------------------------------
__device__ float g_qkv [BATCH * SEQ * QKV3];    // [b, n, 768]
__device__ float g_bias[HEADS * SEQ * SEQ];     // [h, i, j], pre-scaled by log2(e)
__device__ float g_attn[BATCH * SEQ * INNER];   // [b, n, h*32+d]

// ---------------- helpers ----------------------------------------------------
__device__ __forceinline__ unsigned f2tf(float x) {
    unsigned r; asm("cvt.rna.tf32.f32 %0, %1;" : "=r"(r) : "f"(x)); return r;
}
__device__ __forceinline__ float fast_exp2(float x) {
    float y; asm("ex2.approx.f32 %0, %1;" : "=f"(y) : "f"(x)); return y;
}
__device__ __forceinline__ void mma8(float4& d, unsigned a0, unsigned a1,
                                     unsigned a2, unsigned a3,
                                     unsigned b0, unsigned b1) {
    asm volatile(
        "mma.sync.aligned.m16n8k8.row.col.f32.tf32.tf32.f32 "
        "{%0,%1,%2,%3}, {%4,%5,%6,%7}, {%8,%9}, {%0,%1,%2,%3};"
        : "+f"(d.x), "+f"(d.y), "+f"(d.z), "+f"(d.w)
        : "r"(a0), "r"(a1), "r"(a2), "r"(a3), "r"(b0), "r"(b1));
}

// ---------------- tf32 tensor-core GEMM: C = A[M,K] @ B[K,N] (+bias) ---------
// CTA tile 128x64, BK=32, 8 warps (4x2), warp tile 32x32.
template<bool HAS_BIAS>
__global__ __launch_bounds__(256) void gemm_tf32(
    const float* __restrict__ A, const float* __restrict__ B,
    const float* __restrict__ bias, float* __restrict__ C,
    int M, int N, int K)
{
    __shared__ unsigned As[128][33];
    __shared__ unsigned Bs[32][65];

    const int tid  = threadIdx.x;
    const int lane = tid & 31, wid = tid >> 5;
    const int wm = wid & 3, wn = wid >> 2;
    const int r = lane >> 2, q = lane & 3;
    const int m0 = blockIdx.y * 128, n0 = blockIdx.x * 64;

    float4 acc[2][4];
#pragma unroll
    for (int mb = 0; mb < 2; mb++)
#pragma unroll
        for (int nb = 0; nb < 4; nb++)
            acc[mb][nb] = make_float4(0.f, 0.f, 0.f, 0.f);

    for (int k0 = 0; k0 < K; k0 += 32) {
        // Stage A tile (128x32) as tf32
#pragma unroll
        for (int p = 0; p < 4; p++) {
            int slot = tid + p * 256;
            int ar = slot >> 3, ac = (slot & 7) * 4;
            float4 v = *(const float4*)(A + (size_t)(m0 + ar) * K + k0 + ac);
            As[ar][ac + 0] = f2tf(v.x); As[ar][ac + 1] = f2tf(v.y);
            As[ar][ac + 2] = f2tf(v.z); As[ar][ac + 3] = f2tf(v.w);
        }
        // Stage B tile (32x64) as tf32
#pragma unroll
        for (int p = 0; p < 2; p++) {
            int slot = tid + p * 256;
            int br = slot >> 4, bc = (slot & 15) * 4;
            float4 v = *(const float4*)(B + (size_t)(k0 + br) * N + n0 + bc);
            Bs[br][bc + 0] = f2tf(v.x); Bs[br][bc + 1] = f2tf(v.y);
            Bs[br][bc + 2] = f2tf(v.z); Bs[br][bc + 3] = f2tf(v.w);
        }
        __syncthreads();

#pragma unroll
        for (int kk = 0; kk < 4; kk++) {
            int k8 = kk * 8;
            unsigned a[2][4], bf[4][2];
#pragma unroll
            for (int mb = 0; mb < 2; mb++) {
                int rb = wm * 32 + mb * 16;
                a[mb][0] = As[rb + r    ][k8 + q];
                a[mb][1] = As[rb + r + 8][k8 + q];
                a[mb][2] = As[rb + r    ][k8 + q + 4];
                a[mb][3] = As[rb + r + 8][k8 + q + 4];
            }
#pragma unroll
            for (int nb = 0; nb < 4; nb++) {
                int col = wn * 32 + nb * 8 + r;
                bf[nb][0] = Bs[k8 + q    ][col];
                bf[nb][1] = Bs[k8 + q + 4][col];
            }
#pragma unroll
            for (int mb = 0; mb < 2; mb++)
#pragma unroll
                for (int nb = 0; nb < 4; nb++)
                    mma8(acc[mb][nb], a[mb][0], a[mb][1], a[mb][2], a[mb][3],
                         bf[nb][0], bf[nb][1]);
        }
        __syncthreads();
    }

#pragma unroll
    for (int mb = 0; mb < 2; mb++) {
        int row = m0 + wm * 32 + mb * 16 + r;
#pragma unroll
        for (int nb = 0; nb < 4; nb++) {
            int col = n0 + wn * 32 + nb * 8 + 2 * q;
            float b0v = 0.f, b1v = 0.f;
            if (HAS_BIAS) { b0v = bias[col]; b1v = bias[col + 1]; }
            C[(size_t)row * N + col]           = acc[mb][nb].x + b0v;
            C[(size_t)row * N + col + 1]       = acc[mb][nb].y + b1v;
            C[(size_t)(row + 8) * N + col]     = acc[mb][nb].z + b0v;
            C[(size_t)(row + 8) * N + col + 1] = acc[mb][nb].w + b1v;
        }
    }
}

// ---------------- bias expand (pre-scaled by log2 e) -------------------------
__global__ __launch_bounds__(256) void bias_expand_kernel(
    const int* __restrict__ rel, const float* __restrict__ table)
{
    int ij = blockIdx.x * blockDim.x + threadIdx.x;   // 0..1048575
    int idx = rel[ij];
    const float* t = table + idx * 8;
#pragma unroll
    for (int h = 0; h < HEADS; h++)
        g_bias[(size_t)h * (SEQ * SEQ) + ij] = __ldg(t + h) * L2E;
}

// ---------------- tf32 flash attention ---------------------------------------
// CTA: 64 query rows, 4 warps (16 rows each). grid (16, 8, 16).
__global__ __launch_bounds__(128) void attn_tf32()
{
    __shared__ unsigned Ks[64][33];   // tf32 K tile [j][d]
    __shared__ unsigned Vs[64][33];   // tf32 V tile [j][d]
    __shared__ float    Bi[64][68];   // bias tile; stride 68 floats = 272B (16B-aligned rows)

    const int it = blockIdx.x, h = blockIdx.y, b = blockIdx.z;
    const int tid  = threadIdx.x;
    const int lane = tid & 31, wid = tid >> 5;
    const int r = lane >> 2, q = lane & 3;
    const int i0 = it * 64;
    const int iw = wid * 16;

    // Q fragments, pre-scaled by SCALE*log2(e), resident for whole kernel
    unsigned qf[4][4];
    {
        const float qs = SCALE * L2E;
        const float* qb = g_qkv + (size_t)(b * SEQ + i0 + iw) * QKV3 + h * 32;
#pragma unroll
        for (int kb = 0; kb < 4; kb++) {
            qf[kb][0] = f2tf(qs * qb[(size_t)r       * QKV3 + kb * 8 + q]);
            qf[kb][1] = f2tf(qs * qb[(size_t)(r + 8) * QKV3 + kb * 8 + q]);
            qf[kb][2] = f2tf(qs * qb[(size_t)r       * QKV3 + kb * 8 + q + 4]);
            qf[kb][3] = f2tf(qs * qb[(size_t)(r + 8) * QKV3 + kb * 8 + q + 4]);
        }
    }

    float4 o[4];
#pragma unroll
    for (int nb = 0; nb < 4; nb++) o[nb] = make_float4(0.f, 0.f, 0.f, 0.f);
    float m0r = -1e30f, m1r = -1e30f, l0 = 0.f, l1 = 0.f;

    for (int jt = 0; jt < 16; jt++) {
        const int j0 = jt * 64;
        // Stage K/V tiles (64x32) as tf32
#pragma unroll
        for (int p = 0; p < 4; p++) {
            int slot = tid + p * 128;
            int row = slot >> 3, c4 = (slot & 7) * 4;
            const float* kp = g_qkv + (size_t)(b * SEQ + j0 + row) * QKV3
                              + INNER + h * 32 + c4;
            float4 kv = *(const float4*)kp;
            float4 vv = *(const float4*)(kp + INNER);
            Ks[row][c4 + 0] = f2tf(kv.x); Ks[row][c4 + 1] = f2tf(kv.y);
            Ks[row][c4 + 2] = f2tf(kv.z); Ks[row][c4 + 3] = f2tf(kv.w);
            Vs[row][c4 + 0] = f2tf(vv.x); Vs[row][c4 + 1] = f2tf(vv.y);
            Vs[row][c4 + 2] = f2tf(vv.z); Vs[row][c4 + 3] = f2tf(vv.w);
        }
        // Stage bias tile (64x64)
#pragma unroll
        for (int p = 0; p < 8; p++) {
            int slot = tid + p * 128;
            int row = slot >> 4, c4 = (slot & 15) * 4;
            *(float4*)&Bi[row][c4] =
                *(const float4*)(g_bias + (size_t)h * SEQ * SEQ
                                 + (size_t)(i0 + row) * SEQ + j0 + c4);
        }
        __syncthreads();

        // S = (scaled Q) K^T, accumulator seeded with the bias tile
        float4 s[8];
#pragma unroll
        for (int nb = 0; nb < 8; nb++) {
            int col = nb * 8 + 2 * q;
            s[nb].x = Bi[iw + r    ][col];     s[nb].y = Bi[iw + r    ][col + 1];
            s[nb].z = Bi[iw + r + 8][col];     s[nb].w = Bi[iw + r + 8][col + 1];
#pragma unroll
            for (int kb = 0; kb < 4; kb++) {
                unsigned b0 = Ks[nb * 8 + r][kb * 8 + q];
                unsigned b1 = Ks[nb * 8 + r][kb * 8 + q + 4];
                mma8(s[nb], qf[kb][0], qf[kb][1], qf[kb][2], qf[kb][3], b0, b1);
            }
        }

        // online softmax (base-2 domain)
        float t0 = -1e30f, t1 = -1e30f;
#pragma unroll
        for (int nb = 0; nb < 8; nb++) {
            t0 = fmaxf(t0, fmaxf(s[nb].x, s[nb].y));
            t1 = fmaxf(t1, fmaxf(s[nb].z, s[nb].w));
        }
        t0 = fmaxf(t0, __shfl_xor_sync(0xffffffffu, t0, 1));
        t0 = fmaxf(t0, __shfl_xor_sync(0xffffffffu, t0, 2));
        t1 = fmaxf(t1, __shfl_xor_sync(0xffffffffu, t1, 1));
        t1 = fmaxf(t1, __shfl_xor_sync(0xffffffffu, t1, 2));

        float mn0 = fmaxf(m0r, t0), mn1 = fmaxf(m1r, t1);
        float a0 = fast_exp2(m0r - mn0), a1 = fast_exp2(m1r - mn1);
        m0r = mn0; m1r = mn1;

        float ps0 = 0.f, ps1 = 0.f;
#pragma unroll
        for (int nb = 0; nb < 8; nb++) {
            s[nb].x = fast_exp2(s[nb].x - mn0);
            s[nb].y = fast_exp2(s[nb].y - mn0);
            s[nb].z = fast_exp2(s[nb].z - mn1);
            s[nb].w = fast_exp2(s[nb].w - mn1);
            ps0 += s[nb].x + s[nb].y;
            ps1 += s[nb].z + s[nb].w;
        }
        ps0 += __shfl_xor_sync(0xffffffffu, ps0, 1);
        ps0 += __shfl_xor_sync(0xffffffffu, ps0, 2);
        ps1 += __shfl_xor_sync(0xffffffffu, ps1, 1);
        ps1 += __shfl_xor_sync(0xffffffffu, ps1, 2);
        l0 = l0 * a0 + ps0;
        l1 = l1 * a1 + ps1;
#pragma unroll
        for (int nb = 0; nb < 4; nb++) {
            o[nb].x *= a0; o[nb].y *= a0; o[nb].z *= a1; o[nb].w *= a1;
        }

        // O += P V  (j-permutation kappa: slot q -> col 2q, slot q+4 -> col 2q+1,
        // applied identically to the P A-fragment and V B-fragment rows)
#pragma unroll
        for (int kb = 0; kb < 8; kb++) {
            unsigned pa0 = f2tf(s[kb].x), pa1 = f2tf(s[kb].z);
            unsigned pa2 = f2tf(s[kb].y), pa3 = f2tf(s[kb].w);
#pragma unroll
            for (int nb = 0; nb < 4; nb++) {
                int col = nb * 8 + r;
                unsigned b0 = Vs[kb * 8 + 2 * q    ][col];
                unsigned b1 = Vs[kb * 8 + 2 * q + 1][col];
                mma8(o[nb], pa0, pa1, pa2, pa3, b0, b1);
            }
        }
        __syncthreads();
    }

    const float inv0 = 1.f / l0, inv1 = 1.f / l1;
    float* ob = g_attn + (size_t)(b * SEQ + i0 + iw) * INNER + h * 32;
#pragma unroll
    for (int nb = 0; nb < 4; nb++) {
        int col = nb * 8 + 2 * q;
        ob[(size_t)r       * INNER + col]     = o[nb].x * inv0;
        ob[(size_t)r       * INNER + col + 1] = o[nb].y * inv0;
        ob[(size_t)(r + 8) * INNER + col]     = o[nb].z * inv1;
        ob[(size_t)(r + 8) * INNER + col + 1] = o[nb].w * inv1;
    }
}

// ---------------- launch -----------------------------------------------------
extern "C" void kernel_launch(void* const* d_in, const int* in_sizes, int n_in,
                              void* d_out, int out_size)
{
    const float* x      = (const float*)d_in[0];   // [16,1024,384]
    const float* w_qkv  = (const float*)d_in[1];   // [384,768]
    const float* table  = (const float*)d_in[2];   // [3969,8]
    const float* w_out  = (const float*)d_in[3];   // [256,384]
    const float* b_out  = (const float*)d_in[4];   // [384]
    const int*   relidx = (const int*)  d_in[5];   // [1024,1024]
    float* out = (float*)d_out;                    // [16,1024,384]

    float* qkv_ptr  = nullptr;
    float* attn_ptr = nullptr;
    cudaGetSymbolAddress((void**)&qkv_ptr,  g_qkv);
    cudaGetSymbolAddress((void**)&attn_ptr, g_attn);

    const int M = BATCH * SEQ;   // 16384

    // 1) qkv = x @ w_qkv   (tf32 tensor cores)
    gemm_tf32<false><<<dim3(QKV3 / 64, M / 128), 256>>>(
        x, w_qkv, nullptr, qkv_ptr, M, QKV3, INP);

    // 2) expand relative bias per head (pre-scaled by log2 e)
    bias_expand_kernel<<<(SEQ * SEQ) / 256, 256>>>(relidx, table);

    // 3) attention (tf32 tensor cores, flash-style)
    attn_tf32<<<dim3(SEQ / 64, HEADS, BATCH), 128>>>();

    // 4) out = attn @ w_out + b_out  (tf32 tensor cores)
    gemm_tf32<true><<<dim3(OUP / 64, M / 128), 256>>>(
        attn_ptr, w_out, b_out, out, M, OUP, INNER);
}

// round 4
// speedup vs baseline: 3.9488x; 1.7637x over previous
#include <cuda_runtime.h>
#include <cuda_bf16.h>

#define BATCH 16
#define SEQ   1024
#define INP   384
#define HEADS 8
#define INNER 256
#define QKV3  768
#define OUP   384
#define SCALE 0.17677669529663687f
#define L2E   1.4426950408889634f

// ---------------- scratch ----------------------------------------------------
__device__ float g_qkv [BATCH * SEQ * QKV3];    // [b, n, 768]
__device__ float g_bias[HEADS * SEQ * SEQ];     // [h, i, j], pre-scaled by log2(e)
__device__ float g_attn[BATCH * SEQ * INNER];   // [b, n, h*32+d]

// ---------------- helpers ----------------------------------------------------
__device__ __forceinline__ unsigned f2tf(float x) {
    unsigned r; asm("cvt.rna.tf32.f32 %0, %1;" : "=r"(r) : "f"(x)); return r;
}
__device__ __forceinline__ float fast_exp2(float x) {
    float y; asm("ex2.approx.f32 %0, %1;" : "=f"(y) : "f"(x)); return y;
}
__device__ __forceinline__ unsigned sm_u32(const void* p) {
    unsigned r;
    asm("{.reg .u64 t; cvta.to.shared.u64 t, %1; cvt.u32.u64 %0, t;}"
        : "=r"(r) : "l"(p));
    return r;
}
__device__ __forceinline__ void ldsm4(unsigned& r0, unsigned& r1,
                                      unsigned& r2, unsigned& r3, unsigned a) {
    asm volatile("ldmatrix.sync.aligned.m8n8.x4.shared.b16 {%0,%1,%2,%3}, [%4];"
                 : "=r"(r0), "=r"(r1), "=r"(r2), "=r"(r3) : "r"(a));
}
__device__ __forceinline__ void mma8(float4& d, unsigned a0, unsigned a1,
                                     unsigned a2, unsigned a3,
                                     unsigned b0, unsigned b1) {
    asm volatile(
        "mma.sync.aligned.m16n8k8.row.col.f32.tf32.tf32.f32 "
        "{%0,%1,%2,%3}, {%4,%5,%6,%7}, {%8,%9}, {%0,%1,%2,%3};"
        : "+f"(d.x), "+f"(d.y), "+f"(d.z), "+f"(d.w)
        : "r"(a0), "r"(a1), "r"(a2), "r"(a3), "r"(b0), "r"(b1));
}

// ---------------- tf32 tensor-core GEMM: C = A[M,K] @ B[K,N] (+bias) ---------
// CTA tile 128x64, BK=32, 8 warps (4m x 2n), warp tile 32x32.
// A frags + B frags via ldmatrix; register-prefetch double buffering.
template<bool HAS_BIAS>
__global__ __launch_bounds__(256) void gemm_tf32(
    const float* __restrict__ A, const float* __restrict__ B,
    const float* __restrict__ bias, float* __restrict__ C,
    int M, int N, int K)
{
    __shared__ unsigned As[128][36];   // [m][k]  tf32, rows 144B (16B aligned)
    __shared__ unsigned Bt[64][36];    // [n][k]  tf32 (B transposed)

    const int tid  = threadIdx.x;
    const int lane = tid & 31, wid = tid >> 5;
    const int wm = wid & 3, wn = wid >> 2;
    const int r = lane >> 2, q = lane & 3;
    const int m0 = blockIdx.y * 128, n0 = blockIdx.x * 64;
    const int g = lane >> 3;          // ldmatrix tile group 0..3

    // ldmatrix base addresses (per-thread row assignments)
    const unsigned aBase = sm_u32(&As[0][0]) +
        ((unsigned)((wm * 32 + (g & 1) * 8 + (lane & 7)) * 36 + (g >> 1) * 4)) * 4u;
    const unsigned bBase = sm_u32(&Bt[0][0]) +
        ((unsigned)((wn * 32 + (g >> 1) * 8 + (lane & 7)) * 36 + (g & 1) * 4)) * 4u;
    const unsigned TILE_OFF = 16u * 36u * 4u;   // 16 rows

    float4 acc[2][4];
#pragma unroll
    for (int mb = 0; mb < 2; mb++)
#pragma unroll
        for (int nb = 0; nb < 4; nb++)
            acc[mb][nb] = make_float4(0.f, 0.f, 0.f, 0.f);

    const int niter = K / 32;
    float4 pa[4];          // A prefetch: 4 float4 / thread
    float  pb[8];          // B prefetch: 8 scalars / thread (column loads)

    // prefetch tile 0
#pragma unroll
    for (int p = 0; p < 4; p++) {
        int s = tid + p * 256, ar = s >> 3, ac = (s & 7) * 4;
        pa[p] = *(const float4*)(A + (size_t)(m0 + ar) * K + ac);
    }
#pragma unroll
    for (int p = 0; p < 2; p++) {
        int s = tid + p * 256, n = s & 63, k4 = (s >> 6) * 4;
#pragma unroll
        for (int i = 0; i < 4; i++)
            pb[p * 4 + i] = B[(size_t)(k4 + i) * N + n0 + n];
    }

    for (int it = 0; it < niter; it++) {
        __syncthreads();
        // store staged tile (cvt to tf32 here)
#pragma unroll
        for (int p = 0; p < 4; p++) {
            int s = tid + p * 256, ar = s >> 3, ac = (s & 7) * 4;
            uint4 w;
            w.x = f2tf(pa[p].x); w.y = f2tf(pa[p].y);
            w.z = f2tf(pa[p].z); w.w = f2tf(pa[p].w);
            *(uint4*)&As[ar][ac] = w;
        }
#pragma unroll
        for (int p = 0; p < 2; p++) {
            int s = tid + p * 256, n = s & 63, k4 = (s >> 6) * 4;
            uint4 w;
            w.x = f2tf(pb[p * 4 + 0]); w.y = f2tf(pb[p * 4 + 1]);
            w.z = f2tf(pb[p * 4 + 2]); w.w = f2tf(pb[p * 4 + 3]);
            *(uint4*)&Bt[n][k4] = w;
        }
        __syncthreads();

        // prefetch next tile (overlaps with mma work below)
        if (it + 1 < niter) {
            int k0n = (it + 1) * 32;
#pragma unroll
            for (int p = 0; p < 4; p++) {
                int s = tid + p * 256, ar = s >> 3, ac = (s & 7) * 4;
                pa[p] = *(const float4*)(A + (size_t)(m0 + ar) * K + k0n + ac);
            }
#pragma unroll
            for (int p = 0; p < 2; p++) {
                int s = tid + p * 256, n = s & 63, k4 = (s >> 6) * 4;
#pragma unroll
                for (int i = 0; i < 4; i++)
                    pb[p * 4 + i] = B[(size_t)(k0n + k4 + i) * N + n0 + n];
            }
        }

#pragma unroll
        for (int kk = 0; kk < 4; kk++) {
            unsigned a0[4], a1[4], bl[4], bh[4];
            ldsm4(a0[0], a0[1], a0[2], a0[3], aBase + kk * 32);
            ldsm4(a1[0], a1[1], a1[2], a1[3], aBase + kk * 32 + TILE_OFF);
            ldsm4(bl[0], bl[1], bl[2], bl[3], bBase + kk * 32);
            ldsm4(bh[0], bh[1], bh[2], bh[3], bBase + kk * 32 + TILE_OFF);
            mma8(acc[0][0], a0[0], a0[1], a0[2], a0[3], bl[0], bl[1]);
            mma8(acc[0][1], a0[0], a0[1], a0[2], a0[3], bl[2], bl[3]);
            mma8(acc[0][2], a0[0], a0[1], a0[2], a0[3], bh[0], bh[1]);
            mma8(acc[0][3], a0[0], a0[1], a0[2], a0[3], bh[2], bh[3]);
            mma8(acc[1][0], a1[0], a1[1], a1[2], a1[3], bl[0], bl[1]);
            mma8(acc[1][1], a1[0], a1[1], a1[2], a1[3], bl[2], bl[3]);
            mma8(acc[1][2], a1[0], a1[1], a1[2], a1[3], bh[0], bh[1]);
            mma8(acc[1][3], a1[0], a1[1], a1[2], a1[3], bh[2], bh[3]);
        }
    }

#pragma unroll
    for (int mb = 0; mb < 2; mb++) {
        int row = m0 + wm * 32 + mb * 16 + r;
#pragma unroll
        for (int nb = 0; nb < 4; nb++) {
            int col = n0 + wn * 32 + nb * 8 + 2 * q;
            float b0v = 0.f, b1v = 0.f;
            if (HAS_BIAS) { b0v = bias[col]; b1v = bias[col + 1]; }
            float2 lo = make_float2(acc[mb][nb].x + b0v, acc[mb][nb].y + b1v);
            float2 hi = make_float2(acc[mb][nb].z + b0v, acc[mb][nb].w + b1v);
            *(float2*)(C + (size_t)row * N + col)       = lo;
            *(float2*)(C + (size_t)(row + 8) * N + col) = hi;
        }
    }
}

// ---------------- bias expand (pre-scaled by log2 e) -------------------------
__global__ __launch_bounds__(256) void bias_expand_kernel(
    const int* __restrict__ rel, const float* __restrict__ table)
{
    int ij = blockIdx.x * blockDim.x + threadIdx.x;   // 0..1048575
    int idx = rel[ij];
    const float* t = table + idx * 8;
#pragma unroll
    for (int h = 0; h < HEADS; h++)
        g_bias[(size_t)h * (SEQ * SEQ) + ij] = __ldg(t + h) * L2E;
}

// ---------------- tf32 flash attention ---------------------------------------
// CTA: 64 query rows, 4 warps (16 rows each). grid (16, 8, 16).
// K frags via ldmatrix; V frags via conflict-free scalar LDS (kappa perm).
__global__ __launch_bounds__(128) void attn_tf32()
{
    __shared__ unsigned Ks[64][36];   // tf32 K tile [j][d], rows 144B
    __shared__ unsigned Vs[64][36];   // tf32 V tile [j][d]
    __shared__ float    Bi[64][68];   // bias tile (x log2e), rows 272B

    const int it = blockIdx.x, h = blockIdx.y, b = blockIdx.z;
    const int tid  = threadIdx.x;
    const int lane = tid & 31, wid = tid >> 5;
    const int r = lane >> 2, q = lane & 3;
    const int i0 = it * 64;
    const int iw = wid * 16;
    const int g = lane >> 3;

    // ldmatrix base for K fragments:
    // groups g0:(nb even, d lo) g1:(nb even, d hi) g2:(nb odd, d lo) g3:(nb odd, d hi)
    const unsigned kBase = sm_u32(&Ks[0][0]) +
        ((unsigned)(((g >> 1) * 8 + (lane & 7)) * 36 + (g & 1) * 4)) * 4u;
    const unsigned NP_OFF = 16u * 36u * 4u;

    // Q fragments, pre-scaled by SCALE*log2(e)
    unsigned qf[4][4];
    {
        const float qs = SCALE * L2E;
        const float* qb = g_qkv + (size_t)(b * SEQ + i0 + iw) * QKV3 + h * 32;
#pragma unroll
        for (int kb = 0; kb < 4; kb++) {
            qf[kb][0] = f2tf(qs * qb[(size_t)r       * QKV3 + kb * 8 + q]);
            qf[kb][1] = f2tf(qs * qb[(size_t)(r + 8) * QKV3 + kb * 8 + q]);
            qf[kb][2] = f2tf(qs * qb[(size_t)r       * QKV3 + kb * 8 + q + 4]);
            qf[kb][3] = f2tf(qs * qb[(size_t)(r + 8) * QKV3 + kb * 8 + q + 4]);
        }
    }

    float4 o[4];
#pragma unroll
    for (int nb = 0; nb < 4; nb++) o[nb] = make_float4(0.f, 0.f, 0.f, 0.f);
    float m0r = -1e30f, m1r = -1e30f, l0 = 0.f, l1 = 0.f;

    for (int jt = 0; jt < 16; jt++) {
        const int j0 = jt * 64;
        // Stage K/V tiles (64x32) as tf32, vectorized STS
#pragma unroll
        for (int p = 0; p < 4; p++) {
            int slot = tid + p * 128;
            int row = slot >> 3, c4 = (slot & 7) * 4;
            const float* kp = g_qkv + (size_t)(b * SEQ + j0 + row) * QKV3
                              + INNER + h * 32 + c4;
            float4 kv = *(const float4*)kp;
            float4 vv = *(const float4*)(kp + INNER);
            uint4 kw, vw;
            kw.x = f2tf(kv.x); kw.y = f2tf(kv.y); kw.z = f2tf(kv.z); kw.w = f2tf(kv.w);
            vw.x = f2tf(vv.x); vw.y = f2tf(vv.y); vw.z = f2tf(vv.z); vw.w = f2tf(vv.w);
            *(uint4*)&Ks[row][c4] = kw;
            *(uint4*)&Vs[row][c4] = vw;
        }
        // Stage bias tile (64x64)
#pragma unroll
        for (int p = 0; p < 8; p++) {
            int slot = tid + p * 128;
            int row = slot >> 4, c4 = (slot & 15) * 4;
            *(float4*)&Bi[row][c4] =
                *(const float4*)(g_bias + (size_t)h * SEQ * SEQ
                                 + (size_t)(i0 + row) * SEQ + j0 + c4);
        }
        __syncthreads();

        // S = (scaled Q) K^T + bias
        float4 s[8];
#pragma unroll
        for (int nb = 0; nb < 8; nb++) {
            int col = nb * 8 + 2 * q;
            float2 blo = *(const float2*)&Bi[iw + r    ][col];
            float2 bhi = *(const float2*)&Bi[iw + r + 8][col];
            s[nb].x = blo.x; s[nb].y = blo.y; s[nb].z = bhi.x; s[nb].w = bhi.y;
        }
#pragma unroll
        for (int kb = 0; kb < 4; kb++) {
#pragma unroll
            for (int np = 0; np < 4; np++) {
                unsigned b0, b1, b2, b3;
                ldsm4(b0, b1, b2, b3, kBase + np * NP_OFF + kb * 32);
                mma8(s[np * 2 + 0], qf[kb][0], qf[kb][1], qf[kb][2], qf[kb][3], b0, b1);
                mma8(s[np * 2 + 1], qf[kb][0], qf[kb][1], qf[kb][2], qf[kb][3], b2, b3);
            }
        }

        // online softmax (base-2 domain)
        float t0 = -1e30f, t1 = -1e30f;
#pragma unroll
        for (int nb = 0; nb < 8; nb++) {
            t0 = fmaxf(t0, fmaxf(s[nb].x, s[nb].y));
            t1 = fmaxf(t1, fmaxf(s[nb].z, s[nb].w));
        }
        t0 = fmaxf(t0, __shfl_xor_sync(0xffffffffu, t0, 1));
        t0 = fmaxf(t0, __shfl_xor_sync(0xffffffffu, t0, 2));
        t1 = fmaxf(t1, __shfl_xor_sync(0xffffffffu, t1, 1));
        t1 = fmaxf(t1, __shfl_xor_sync(0xffffffffu, t1, 2));

        float mn0 = fmaxf(m0r, t0), mn1 = fmaxf(m1r, t1);
        float a0 = fast_exp2(m0r - mn0), a1 = fast_exp2(m1r - mn1);
        m0r = mn0; m1r = mn1;

        float ps0 = 0.f, ps1 = 0.f;
#pragma unroll
        for (int nb = 0; nb < 8; nb++) {
            s[nb].x = fast_exp2(s[nb].x - mn0);
            s[nb].y = fast_exp2(s[nb].y - mn0);
            s[nb].z = fast_exp2(s[nb].z - mn1);
            s[nb].w = fast_exp2(s[nb].w - mn1);
            ps0 += s[nb].x + s[nb].y;
            ps1 += s[nb].z + s[nb].w;
        }
        ps0 += __shfl_xor_sync(0xffffffffu, ps0, 1);
        ps0 += __shfl_xor_sync(0xffffffffu, ps0, 2);
        ps1 += __shfl_xor_sync(0xffffffffu, ps1, 1);
        ps1 += __shfl_xor_sync(0xffffffffu, ps1, 2);
        l0 = l0 * a0 + ps0;
        l1 = l1 * a1 + ps1;
#pragma unroll
        for (int nb = 0; nb < 4; nb++) {
            o[nb].x *= a0; o[nb].y *= a0; o[nb].z *= a1; o[nb].w *= a1;
        }

        // O += P V  (kappa perm: slot q -> row 2q, slot q+4 -> row 2q+1).
        // Vs stride 36 words: bank = (8q + 8nb + r) mod 32 -> conflict-free.
#pragma unroll
        for (int kb = 0; kb < 8; kb++) {
            unsigned pa0 = f2tf(s[kb].x), pa1 = f2tf(s[kb].z);
            unsigned pa2 = f2tf(s[kb].y), pa3 = f2tf(s[kb].w);
            int jv = kb * 8 + 2 * q;
#pragma unroll
            for (int nb = 0; nb < 4; nb++) {
                int col = nb * 8 + r;
                unsigned b0 = Vs[jv    ][col];
                unsigned b1 = Vs[jv + 1][col];
                mma8(o[nb], pa0, pa1, pa2, pa3, b0, b1);
            }
        }
        __syncthreads();
    }

    const float inv0 = 1.f / l0, inv1 = 1.f / l1;
    float* ob = g_attn + (size_t)(b * SEQ + i0 + iw) * INNER + h * 32;
#pragma unroll
    for (int nb = 0; nb < 4; nb++) {
        int col = nb * 8 + 2 * q;
        float2 lo = make_float2(o[nb].x * inv0, o[nb].y * inv0);
        float2 hi = make_float2(o[nb].z * inv1, o[nb].w * inv1);
        *(float2*)(ob + (size_t)r       * INNER + col) = lo;
        *(float2*)(ob + (size_t)(r + 8) * INNER + col) = hi;
    }
}

// ---------------- launch -----------------------------------------------------
extern "C" void kernel_launch(void* const* d_in, const int* in_sizes, int n_in,
                              void* d_out, int out_size)
{
    const float* x      = (const float*)d_in[0];   // [16,1024,384]
    const float* w_qkv  = (const float*)d_in[1];   // [384,768]
    const float* table  = (const float*)d_in[2];   // [3969,8]
    const float* w_out  = (const float*)d_in[3];   // [256,384]
    const float* b_out  = (const float*)d_in[4];   // [384]
    const int*   relidx = (const int*)  d_in[5];   // [1024,1024]
    float* out = (float*)d_out;                    // [16,1024,384]

    float* qkv_ptr  = nullptr;
    float* attn_ptr = nullptr;
    cudaGetSymbolAddress((void**)&qkv_ptr,  g_qkv);
    cudaGetSymbolAddress((void**)&attn_ptr, g_attn);

    const int M = BATCH * SEQ;   // 16384

    // 1) qkv = x @ w_qkv   (tf32 tensor cores)
    gemm_tf32<false><<<dim3(QKV3 / 64, M / 128), 256>>>(
        x, w_qkv, nullptr, qkv_ptr, M, QKV3, INP);

    // 2) expand relative bias per head (pre-scaled by log2 e)
    bias_expand_kernel<<<(SEQ * SEQ) / 256, 256>>>(relidx, table);

    // 3) attention (tf32 tensor cores, flash-style)
    attn_tf32<<<dim3(SEQ / 64, HEADS, BATCH), 128>>>();

    // 4) out = attn @ w_out + b_out  (tf32 tensor cores)
    gemm_tf32<true><<<dim3(OUP / 64, M / 128), 256>>>(
        attn_ptr, w_out, b_out, out, M, OUP, INNER);
}